// round 4
// baseline (speedup 1.0000x reference)
#include <cuda_runtime.h>
#include <cuda_fp16.h>
#include <cstdint>

// ---------------------------------------------------------------------------
// Seq2Seq RNN (tanh), B=1024, T=128, H=512, L=4, PRED_LEN=10.
// Round 4: L2-traffic-first redesign. 128x128 CTA tiles (2x less L2 traffic),
// weights kept [n][k] (non-trans ldmatrix for B), single-sync 2-stage
// cp.async pipeline. Split-fp16 (hi/lo, 3 products) mma.sync, fp32 accum.
// Encoder anti-diagonal wavefront launches; serial decoder; FC head.
// ---------------------------------------------------------------------------

#define ACT_L 67108864LL  // halves per (layer, hi/lo) activation plane

static __device__ __half g_act[8LL * ACT_L];   // [4 layers][2 hi/lo][b=1024][t=128][k=512]
static __device__ __half g_wenc_hi[2097152];   // [4][512 n][1024 k] (k = Wih|Whh)
static __device__ __half g_wenc_lo[2097152];
static __device__ __half g_wdec_hi[2097152];
static __device__ __half g_wdec_lo[2097152];
static __device__ __half g_dh_hi[4194304];     // [2][4][1024][512]
static __device__ __half g_dh_lo[4194304];
static __device__ float  g_decout[5242880];    // [1024][10][512]

__device__ __forceinline__ uint32_t smem_u32(const void* p) {
    return (uint32_t)__cvta_generic_to_shared(p);
}

__device__ __forceinline__ void cp16(uint32_t saddr, const void* g) {
    asm volatile("cp.async.cg.shared.global [%0], [%1], 16;\n" :: "r"(saddr), "l"(g));
}

__device__ __forceinline__ void mma16816(float* c,
                                         uint32_t a0, uint32_t a1, uint32_t a2, uint32_t a3,
                                         uint32_t b0, uint32_t b1) {
    asm volatile(
        "mma.sync.aligned.m16n8k16.row.col.f32.f16.f16.f32 "
        "{%0,%1,%2,%3}, {%4,%5,%6,%7}, {%8,%9}, {%0,%1,%2,%3};"
        : "+f"(c[0]), "+f"(c[1]), "+f"(c[2]), "+f"(c[3])
        : "r"(a0), "r"(a1), "r"(a2), "r"(a3), "r"(b0), "r"(b1));
}

__device__ __forceinline__ void ldsm_x4(uint32_t addr, uint32_t& r0, uint32_t& r1,
                                        uint32_t& r2, uint32_t& r3) {
    asm volatile("ldmatrix.sync.aligned.m8n8.x4.shared.b16 {%0,%1,%2,%3}, [%4];"
                 : "=r"(r0), "=r"(r1), "=r"(r2), "=r"(r3) : "r"(addr));
}

// Dynamic smem: sA [2 buf][2 plane][128 row][40], sB same. 81920 bytes total.
#define SMEM_BYTES 81920
#define A_OFF(buf, plane, row, col) ((((buf) * 2 + (plane)) * 128 + (row)) * 40 + (col))

// out = tanh(X@Wih^T + H@Whh^T + bih + bhh). Weight k in [0,512) = X part,
// [512,1024) = H part. kstart=512 skips X GEMM (layer-0 raw input via Xraw).
__device__ __forceinline__ void step_core(
    __half* sA, __half* sB, int bm0, int bn0,
    const __half* __restrict__ Xhi, const __half* __restrict__ Xlo, long long ldx,
    const __half* __restrict__ Hhi, const __half* __restrict__ Hlo, long long ldh,
    const __half* __restrict__ Whi, const __half* __restrict__ Wlo,
    const float* __restrict__ bih, const float* __restrict__ bhh,
    __half* __restrict__ outHi, __half* __restrict__ outLo, long long ldoh,
    float* __restrict__ out32, long long ldo32,
    int kstart, int kend,
    const float* __restrict__ Xraw, long long ldxraw, const float* __restrict__ Wih0)
{
    const int tid = threadIdx.x;
    const int lane = tid & 31;
    const int warp = tid >> 5;
    const int wm = (warp & 1) * 64;    // 2 warps along M (64 rows each)
    const int wn = (warp >> 1) * 32;   // 4 warps along N (32 cols each)

    float acc[4][4][4];
#pragma unroll
    for (int a = 0; a < 4; ++a)
#pragma unroll
        for (int b = 0; b < 4; ++b)
#pragma unroll
            for (int q = 0; q < 4; ++q) acc[a][b][q] = 0.f;

    if (Xraw) {  // layer-0 input projection (K=6), direct fp32
#pragma unroll
        for (int mt = 0; mt < 4; ++mt)
#pragma unroll
            for (int i = 0; i < 2; ++i) {
                const int m = bm0 + wm + mt * 16 + (lane >> 2) + i * 8;
                float xr[6];
#pragma unroll
                for (int k = 0; k < 6; ++k) xr[k] = Xraw[(long long)m * ldxraw + k];
#pragma unroll
                for (int nt = 0; nt < 4; ++nt)
#pragma unroll
                    for (int j = 0; j < 2; ++j) {
                        const int n = bn0 + wn + ((nt >> 1) << 4) + ((nt & 1) << 3)
                                      + (lane & 3) * 2 + j;
#pragma unroll
                        for (int k = 0; k < 6; ++k)
                            acc[mt][nt][i * 2 + j] += xr[k] * Wih0[n * 6 + k];
                    }
            }
    }

    const int nkb = (kend - kstart) >> 5;

    auto issue = [&](int kb) {
        const int k0 = kstart + kb * 32;
        const int buf = kb & 1;
        const __half *ah, *al;
        long long la;
        int kk0;
        if (k0 < 512) { ah = Xhi; al = Xlo; la = ldx; kk0 = k0; }
        else          { ah = Hhi; al = Hlo; la = ldh; kk0 = k0 - 512; }
#pragma unroll
        for (int i = 0; i < 2; ++i) {
            const int task = tid + 256 * i;
            const int row = task >> 2;
            const int ch = (task & 3) * 8;
            const long long ga = (long long)(bm0 + row) * la + kk0 + ch;
            cp16(smem_u32(&sA[A_OFF(buf, 0, row, ch)]), ah + ga);
            cp16(smem_u32(&sA[A_OFF(buf, 1, row, ch)]), al + ga);
            const long long gb = (long long)(bn0 + row) * 1024 + k0 + ch;
            cp16(smem_u32(&sB[A_OFF(buf, 0, row, ch)]), Whi + gb);
            cp16(smem_u32(&sB[A_OFF(buf, 1, row, ch)]), Wlo + gb);
        }
    };

    if (nkb > 0) {
        issue(0);
        asm volatile("cp.async.commit_group;\n" ::: "memory");
        for (int kb = 0; kb < nkb; ++kb) {
            asm volatile("cp.async.wait_group 0;\n" ::: "memory");
            __syncthreads();
            if (kb + 1 < nkb) {
                issue(kb + 1);
                asm volatile("cp.async.commit_group;\n" ::: "memory");
            }
            const int buf = kb & 1;
            __half* Ah = sA + A_OFF(buf, 0, 0, 0);
            __half* Al = sA + A_OFF(buf, 1, 0, 0);
            __half* Bh = sB + A_OFF(buf, 0, 0, 0);
            __half* Bl = sB + A_OFF(buf, 1, 0, 0);
#pragma unroll
            for (int kk = 0; kk < 32; kk += 16) {
                const int lrow = lane & 15;
                const int lcol = kk + ((lane >> 4) << 3);
                // cache B fragments (hi+lo) for this warp's 32 n-cols
                uint32_t bh[2][4], bl[2][4];
#pragma unroll
                for (int bg = 0; bg < 2; ++bg) {
                    const int br = wn + bg * 16 + lrow;
                    ldsm_x4(smem_u32(&Bh[br * 40 + lcol]),
                            bh[bg][0], bh[bg][1], bh[bg][2], bh[bg][3]);
                    ldsm_x4(smem_u32(&Bl[br * 40 + lcol]),
                            bl[bg][0], bl[bg][1], bl[bg][2], bl[bg][3]);
                }
#pragma unroll
                for (int mt = 0; mt < 4; ++mt) {
                    const int ar = wm + mt * 16 + lrow;
                    uint32_t ah0, ah1, ah2, ah3, al0, al1, al2, al3;
                    ldsm_x4(smem_u32(&Ah[ar * 40 + lcol]), ah0, ah1, ah2, ah3);
                    ldsm_x4(smem_u32(&Al[ar * 40 + lcol]), al0, al1, al2, al3);
#pragma unroll
                    for (int bg = 0; bg < 2; ++bg) {
                        float* c0 = acc[mt][bg * 2 + 0];
                        float* c1 = acc[mt][bg * 2 + 1];
                        mma16816(c0, ah0, ah1, ah2, ah3, bh[bg][0], bh[bg][2]);
                        mma16816(c1, ah0, ah1, ah2, ah3, bh[bg][1], bh[bg][3]);
                        mma16816(c0, al0, al1, al2, al3, bh[bg][0], bh[bg][2]);
                        mma16816(c1, al0, al1, al2, al3, bh[bg][1], bh[bg][3]);
                        mma16816(c0, ah0, ah1, ah2, ah3, bl[bg][0], bl[bg][2]);
                        mma16816(c1, ah0, ah1, ah2, ah3, bl[bg][1], bl[bg][3]);
                    }
                }
            }
            __syncthreads();
        }
    }

    // epilogue: bias + tanh + producer-side split store (+ optional fp32)
#pragma unroll
    for (int mt = 0; mt < 4; ++mt)
#pragma unroll
        for (int nt = 0; nt < 4; ++nt)
#pragma unroll
            for (int i = 0; i < 2; ++i)
#pragma unroll
                for (int j = 0; j < 2; ++j) {
                    const int m = bm0 + wm + mt * 16 + (lane >> 2) + i * 8;
                    const int n = bn0 + wn + ((nt >> 1) << 4) + ((nt & 1) << 3)
                                  + (lane & 3) * 2 + j;
                    const float v = tanhf(acc[mt][nt][i * 2 + j] + bih[n] + bhh[n]);
                    const __half hi = __float2half_rn(v);
                    const __half lo = __float2half_rn(v - __half2float(hi));
                    outHi[(long long)m * ldoh + n] = hi;
                    outLo[(long long)m * ldoh + n] = lo;
                    if (out32) out32[(long long)m * ldo32 + n] = v;
                }
}

// Encoder wavefront diagonal d: blockIdx.z = layer - l_base, tile = (bx, by).
__global__ void __launch_bounds__(256, 2) enc_diag_kernel(
    int d, int l_base,
    const float* __restrict__ xraw, const float* __restrict__ Wih0,
    const float* __restrict__ ebih, const float* __restrict__ ebhh,
    float* __restrict__ enc_out)
{
    extern __shared__ __half smem[];
    __half* sA = smem;
    __half* sB = smem + 20480;

    const int l = l_base + blockIdx.z;
    const int t = d - l;
    const int bm0 = blockIdx.x * 128;
    const int bn0 = blockIdx.y * 128;

    const __half* Whi = g_wenc_hi + (long long)l * 524288;
    const __half* Wlo = g_wenc_lo + (long long)l * 524288;
    __half* actl_hi = g_act + ((long long)l * 2 + 0) * ACT_L;
    __half* actl_lo = g_act + ((long long)l * 2 + 1) * ACT_L;

    const __half *Xhi = nullptr, *Xlo = nullptr, *Hhi = nullptr, *Hlo = nullptr;
    long long ldx = 0;
    int kstart = 512, kend = 512;
    const float* Xr = nullptr;

    if (l == 0) {
        Xr = xraw + (long long)t * 6;
    } else {
        const __half* prev = g_act + ((long long)(l - 1) * 2) * ACT_L;
        Xhi = prev + (long long)t * 512;
        Xlo = prev + ACT_L + (long long)t * 512;
        ldx = 65536;
        kstart = 0;
    }
    if (t > 0) {
        Hhi = actl_hi + (long long)(t - 1) * 512;
        Hlo = actl_lo + (long long)(t - 1) * 512;
        kend = 1024;
    }
    float* o32 = (l == 3) ? enc_out + (long long)t * 512 : nullptr;

    step_core(sA, sB, bm0, bn0, Xhi, Xlo, ldx, Hhi, Hlo, 65536,
              Whi, Wlo, ebih + l * 512, ebhh + l * 512,
              actl_hi + (long long)t * 512, actl_lo + (long long)t * 512, 65536,
              o32, 65536, kstart, kend, Xr, 768, Wih0);
}

__global__ void __launch_bounds__(256, 2) dec_step_kernel(
    const __half* __restrict__ Xhi, const __half* __restrict__ Xlo, long long ldx,
    const __half* __restrict__ Hhi, const __half* __restrict__ Hlo, long long ldh,
    const __half* __restrict__ Whi, const __half* __restrict__ Wlo,
    const float* __restrict__ bih, const float* __restrict__ bhh,
    __half* __restrict__ outHi, __half* __restrict__ outLo,
    float* __restrict__ out32, long long ldo32)
{
    extern __shared__ __half smem[];
    __half* sA = smem;
    __half* sB = smem + 20480;
    step_core(sA, sB, blockIdx.x * 128, blockIdx.y * 128,
              Xhi, Xlo, ldx, Hhi, Hlo, ldh, Whi, Wlo, bih, bhh,
              outHi, outLo, 512, out32, ldo32, 0, 1024, nullptr, 0, nullptr);
}

// Split all weights once into fp16 hi/lo, layout [l][n][k] with k = [Wih|Whh].
__global__ void __launch_bounds__(256) prep_kernel(
    const float* __restrict__ eWih, const float* __restrict__ eWhh,
    const float* __restrict__ dWih, const float* __restrict__ dWhh)
{
    const unsigned idx = blockIdx.x * 256 + threadIdx.x;
    const int model = idx >> 21;
    const unsigned j = idx & 0x1FFFFFu;
    const int l = j >> 19;
    const int n = (j >> 10) & 511;
    const int k = j & 1023;
    float v;
    if (!model) {
        if (k < 512) v = (l == 0) ? 0.f : eWih[((unsigned)(l - 1) * 512 + n) * 512 + k];
        else         v = eWhh[((unsigned)l * 512 + n) * 512 + (k - 512)];
    } else {
        if (k < 512) v = dWih[((unsigned)l * 512 + n) * 512 + k];
        else         v = dWhh[((unsigned)l * 512 + n) * 512 + (k - 512)];
    }
    const __half hi = __float2half_rn(v);
    const __half lo = __float2half_rn(v - __half2float(hi));
    if (!model) { g_wenc_hi[j] = hi; g_wenc_lo[j] = lo; }
    else        { g_wdec_hi[j] = hi; g_wdec_lo[j] = lo; }
}

// outputs[r, n] = decout[r, :] @ fcW[n, :] + fcb[n]
__global__ void __launch_bounds__(256) fc_kernel(
    const float* __restrict__ in, const float* __restrict__ W,
    const float* __restrict__ b, float* __restrict__ out)
{
    __shared__ float Ws[6 * 512];
    const int tid = threadIdx.x;
    for (int i = tid; i < 6 * 512; i += 256) Ws[i] = W[i];
    __syncthreads();

    const int warp = tid >> 5, lane = tid & 31;
    const int row = blockIdx.x * 8 + warp;
    float p[6] = {0.f, 0.f, 0.f, 0.f, 0.f, 0.f};
    for (int k = lane; k < 512; k += 32) {
        const float v = in[(long long)row * 512 + k];
#pragma unroll
        for (int n = 0; n < 6; ++n) p[n] += v * Ws[n * 512 + k];
    }
#pragma unroll
    for (int off = 16; off > 0; off >>= 1)
#pragma unroll
        for (int n = 0; n < 6; ++n)
            p[n] += __shfl_down_sync(0xffffffffu, p[n], off);
    if (lane == 0) {
#pragma unroll
        for (int n = 0; n < 6; ++n) out[(long long)row * 6 + n] = p[n] + b[n];
    }
}

extern "C" void kernel_launch(void* const* d_in, const int* in_sizes, int n_in,
                              void* d_out, int out_size) {
    const float* x     = (const float*)d_in[0];
    const float* eWih0 = (const float*)d_in[1];
    const float* eWih  = (const float*)d_in[2];
    const float* eWhh  = (const float*)d_in[3];
    const float* ebih  = (const float*)d_in[4];
    const float* ebhh  = (const float*)d_in[5];
    const float* dWih  = (const float*)d_in[6];
    const float* dWhh  = (const float*)d_in[7];
    const float* dbih  = (const float*)d_in[8];
    const float* dbhh  = (const float*)d_in[9];
    const float* fcW   = (const float*)d_in[10];
    const float* fcb   = (const float*)d_in[11];

    float* out = (float*)d_out;
    float* enc_out = out;               // [1024,128,512]
    float* outputs = out + 67108864LL;  // [1024,10,6]

    __half *actB, *dhHi, *dhLo, *wdHi, *wdLo;
    float* decout;
    cudaGetSymbolAddress((void**)&actB, g_act);
    cudaGetSymbolAddress((void**)&dhHi, g_dh_hi);
    cudaGetSymbolAddress((void**)&dhLo, g_dh_lo);
    cudaGetSymbolAddress((void**)&wdHi, g_wdec_hi);
    cudaGetSymbolAddress((void**)&wdLo, g_wdec_lo);
    cudaGetSymbolAddress((void**)&decout, g_decout);

    static bool configured = false;
    if (!configured) {
        cudaFuncSetAttribute(enc_diag_kernel,
                             cudaFuncAttributeMaxDynamicSharedMemorySize, SMEM_BYTES);
        cudaFuncSetAttribute(dec_step_kernel,
                             cudaFuncAttributeMaxDynamicSharedMemorySize, SMEM_BYTES);
        configured = true;
    }

    // 1) weight split (no transpose)
    prep_kernel<<<16384, 256>>>(eWih, eWhh, dWih, dWhh);

    // 2) encoder wavefront: 131 diagonals, 128x128 tiles
    for (int d = 0; d < 131; ++d) {
        const int llo = (d > 127) ? d - 127 : 0;
        const int lhi = (d < 3) ? d : 3;
        dim3 grid(8, 4, lhi - llo + 1);
        enc_diag_kernel<<<grid, 256, SMEM_BYTES>>>(d, llo, x, eWih0, ebih, ebhh, enc_out);
    }

    // 3) decoder: 10 steps x 4 layers, serial
    const dim3 dgrid(8, 4);
    for (int s = 0; s < 10; ++s) {
        const int wset = s & 1;
        const int rset = (s - 1) & 1;
        for (int l = 0; l < 4; ++l) {
            const __half *Xhi, *Xlo, *Hhi, *Hlo;
            long long ldx, ldh;
            if (l == 0) {
                if (s == 0) {
                    Xhi = actB + 6 * ACT_L + 127LL * 512;
                    Xlo = actB + 7 * ACT_L + 127LL * 512;
                    ldx = 65536;
                } else {
                    Xhi = dhHi + ((long long)rset * 4 + 3) * 524288;
                    Xlo = dhLo + ((long long)rset * 4 + 3) * 524288;
                    ldx = 512;
                }
            } else {
                Xhi = dhHi + ((long long)wset * 4 + (l - 1)) * 524288;
                Xlo = dhLo + ((long long)wset * 4 + (l - 1)) * 524288;
                ldx = 512;
            }
            if (s == 0) {
                Hhi = actB + ((long long)l * 2 + 0) * ACT_L + 127LL * 512;
                Hlo = actB + ((long long)l * 2 + 1) * ACT_L + 127LL * 512;
                ldh = 65536;
            } else {
                Hhi = dhHi + ((long long)rset * 4 + l) * 524288;
                Hlo = dhLo + ((long long)rset * 4 + l) * 524288;
                ldh = 512;
            }
            __half* oHi = dhHi + ((long long)wset * 4 + l) * 524288;
            __half* oLo = dhLo + ((long long)wset * 4 + l) * 524288;
            float* o32 = (l == 3) ? decout + (long long)s * 512 : nullptr;
            dec_step_kernel<<<dgrid, 256, SMEM_BYTES>>>(
                Xhi, Xlo, ldx, Hhi, Hlo, ldh,
                wdHi + (long long)l * 524288, wdLo + (long long)l * 524288,
                dbih + l * 512, dbhh + l * 512, oHi, oLo, o32, 5120);
        }
    }

    // 4) FC head
    fc_kernel<<<1280, 256>>>(decout, fcW, fcb, outputs);
}

// round 7
// speedup vs baseline: 1.1731x; 1.1731x over previous
#include <cuda_runtime.h>
#include <cuda_fp16.h>
#include <cstdint>

// ---------------------------------------------------------------------------
// Seq2Seq RNN (tanh), B=1024, T=128, H=512, L=4, PRED_LEN=10.
// Round 7: mma.sync HMMA path (tcgen05 unavailable: harness ptxas targets
// sm_103 without the 'a' suffix). R2 skeleton (64x64 tiles, wavefront
// encoder) + 6-ldsm register-cached mainloop + 3-stage single-sync cp.async
// pipeline + [n][k] weights (non-trans ldsm for B).
// Split-fp16 (hi/lo, 3 products) GEMM, fp32 accumulate.
// ---------------------------------------------------------------------------

#define ACT_L 67108864LL  // halves per (layer, hi/lo) activation plane

static __device__ __half g_act[8LL * ACT_L];   // [4 layers][2 hi/lo][b*t][512]
static __device__ __half g_wenc_hi[2097152];   // [4][512 n][1024 k] (k = Wih|Whh)
static __device__ __half g_wenc_lo[2097152];
static __device__ __half g_wdec_hi[2097152];
static __device__ __half g_wdec_lo[2097152];
static __device__ __half g_dh_hi[4194304];     // [2][4][1024][512]
static __device__ __half g_dh_lo[4194304];
static __device__ float  g_decout[5242880];    // [1024][10][512]

// Dynamic smem: 3 stages x 4 planes (Ah, Al, Bh, Bl) x 64 rows x 40-half pitch.
#define STAGE_H   10240                 // halves per stage
#define SMEM_BYTES (3 * STAGE_H * 2)    // 61440 bytes
#define PL_AH 0
#define PL_AL 2560
#define PL_BH 5120
#define PL_BL 7680

__device__ __forceinline__ uint32_t smem_u32(const void* p) {
    return (uint32_t)__cvta_generic_to_shared(p);
}

__device__ __forceinline__ void cp16(uint32_t saddr, const void* g) {
    asm volatile("cp.async.cg.shared.global [%0], [%1], 16;\n" :: "r"(saddr), "l"(g));
}

__device__ __forceinline__ void mma16816(float* c,
                                         uint32_t a0, uint32_t a1, uint32_t a2, uint32_t a3,
                                         uint32_t b0, uint32_t b1) {
    asm volatile(
        "mma.sync.aligned.m16n8k16.row.col.f32.f16.f16.f32 "
        "{%0,%1,%2,%3}, {%4,%5,%6,%7}, {%8,%9}, {%0,%1,%2,%3};"
        : "+f"(c[0]), "+f"(c[1]), "+f"(c[2]), "+f"(c[3])
        : "r"(a0), "r"(a1), "r"(a2), "r"(a3), "r"(b0), "r"(b1));
}

__device__ __forceinline__ void ldsm_x4(uint32_t addr, uint32_t& r0, uint32_t& r1,
                                        uint32_t& r2, uint32_t& r3) {
    asm volatile("ldmatrix.sync.aligned.m8n8.x4.shared.b16 {%0,%1,%2,%3}, [%4];"
                 : "=r"(r0), "=r"(r1), "=r"(r2), "=r"(r3) : "r"(addr));
}

// out = tanh(X@Wih^T + H@Whh^T + bih + bhh). Weight k in [0,512) = X part,
// [512,1024) = H part. W layout [n][k], ld 1024.
__device__ __forceinline__ void step_core(
    __half* sm, int bm0, int bn0,
    const __half* __restrict__ Xhi, const __half* __restrict__ Xlo, long long ldx,
    const __half* __restrict__ Hhi, const __half* __restrict__ Hlo, long long ldh,
    const __half* __restrict__ Whi, const __half* __restrict__ Wlo,
    const float* __restrict__ bih, const float* __restrict__ bhh,
    __half* __restrict__ outHi, __half* __restrict__ outLo, long long ldoh,
    float* __restrict__ out32, long long ldo32,
    int kstart, int kend,
    const float* __restrict__ Xraw, long long ldxraw, const float* __restrict__ Wih0)
{
    const int tid = threadIdx.x;
    const int lane = tid & 31;
    const int warp = tid >> 5;
    const int wm = (warp & 3) * 16;   // 4 warps along M (16 rows each)
    const int wn = (warp >> 2) * 32;  // 2 warps along N (32 cols each)

    float acc[2][2][4];
#pragma unroll
    for (int a = 0; a < 2; ++a)
#pragma unroll
        for (int b = 0; b < 2; ++b)
#pragma unroll
            for (int q = 0; q < 4; ++q) acc[a][b][q] = 0.f;

    if (Xraw) {  // layer-0 input projection (K=6), direct fp32
        float xr[2][6];
#pragma unroll
        for (int i = 0; i < 2; ++i) {
            const int m = bm0 + wm + (lane >> 2) + i * 8;
#pragma unroll
            for (int k = 0; k < 6; ++k) xr[i][k] = Xraw[(long long)m * ldxraw + k];
        }
#pragma unroll
        for (int bg = 0; bg < 2; ++bg)
#pragma unroll
            for (int h = 0; h < 2; ++h)
#pragma unroll
                for (int j = 0; j < 2; ++j) {
                    const int n = bn0 + wn + bg * 16 + h * 8 + (lane & 3) * 2 + j;
#pragma unroll
                    for (int k = 0; k < 6; ++k) {
                        const float w = Wih0[n * 6 + k];
                        acc[bg][h][0 + j] += xr[0][k] * w;
                        acc[bg][h][2 + j] += xr[1][k] * w;
                    }
                }
    }

    const int nkb = (kend - kstart) >> 5;
    const int srow = tid >> 2;            // 0..63
    const int scq = (tid & 3) * 8;        // 0,8,16,24

    auto issue = [&](int cb) {
        const int s = cb % 3;
        const int k0 = kstart + cb * 32;
        const __half *axh, *axl;
        long long la;
        int kloc;
        if (k0 < 512) { axh = Xhi; axl = Xlo; la = ldx; kloc = k0; }
        else          { axh = Hhi; axl = Hlo; la = ldh; kloc = k0 - 512; }
        __half* st = sm + s * STAGE_H;
        const long long ga = (long long)(bm0 + srow) * la + kloc + scq;
        cp16(smem_u32(st + PL_AH + srow * 40 + scq), axh + ga);
        cp16(smem_u32(st + PL_AL + srow * 40 + scq), axl + ga);
        const long long gb = (long long)(bn0 + srow) * 1024 + k0 + scq;
        cp16(smem_u32(st + PL_BH + srow * 40 + scq), Whi + gb);
        cp16(smem_u32(st + PL_BL + srow * 40 + scq), Wlo + gb);
        asm volatile("cp.async.commit_group;" ::: "memory");
    };

    if (nkb > 0) {
        issue(0);
        if (nkb > 1) issue(1);
        for (int kb = 0; kb < nkb; ++kb) {
            if (kb + 1 < nkb) {
                asm volatile("cp.async.wait_group 1;" ::: "memory");
            } else {
                asm volatile("cp.async.wait_group 0;" ::: "memory");
            }
            __syncthreads();
            const __half* st = sm + (kb % 3) * STAGE_H;
#pragma unroll
            for (int kk = 0; kk < 32; kk += 16) {
                const int lrow = lane & 15;
                const int lcol = kk + ((lane >> 4) << 3);
                const int ar = wm + lrow;
                uint32_t ah0, ah1, ah2, ah3, al0, al1, al2, al3;
                ldsm_x4(smem_u32(st + PL_AH + ar * 40 + lcol), ah0, ah1, ah2, ah3);
                ldsm_x4(smem_u32(st + PL_AL + ar * 40 + lcol), al0, al1, al2, al3);
#pragma unroll
                for (int bg = 0; bg < 2; ++bg) {
                    const int br = wn + bg * 16 + lrow;
                    uint32_t bh0, bh1, bh2, bh3, bl0, bl1, bl2, bl3;
                    ldsm_x4(smem_u32(st + PL_BH + br * 40 + lcol), bh0, bh1, bh2, bh3);
                    ldsm_x4(smem_u32(st + PL_BL + br * 40 + lcol), bl0, bl1, bl2, bl3);
                    float* c0 = acc[bg][0];
                    float* c1 = acc[bg][1];
                    mma16816(c0, ah0, ah1, ah2, ah3, bh0, bh2);
                    mma16816(c1, ah0, ah1, ah2, ah3, bh1, bh3);
                    mma16816(c0, al0, al1, al2, al3, bh0, bh2);
                    mma16816(c1, al0, al1, al2, al3, bh1, bh3);
                    mma16816(c0, ah0, ah1, ah2, ah3, bl0, bl2);
                    mma16816(c1, ah0, ah1, ah2, ah3, bl1, bl3);
                }
            }
            __syncthreads();
            if (kb + 2 < nkb) issue(kb + 2);
        }
    }

    // epilogue: bias + tanh + producer-side split store (+ optional fp32)
#pragma unroll
    for (int bg = 0; bg < 2; ++bg)
#pragma unroll
        for (int h = 0; h < 2; ++h)
#pragma unroll
            for (int i = 0; i < 2; ++i)
#pragma unroll
                for (int j = 0; j < 2; ++j) {
                    const int m = bm0 + wm + (lane >> 2) + i * 8;
                    const int n = bn0 + wn + bg * 16 + h * 8 + (lane & 3) * 2 + j;
                    const float v = tanhf(acc[bg][h][i * 2 + j] + bih[n] + bhh[n]);
                    const __half hi = __float2half_rn(v);
                    const __half lo = __float2half_rn(v - __half2float(hi));
                    outHi[(long long)m * ldoh + n] = hi;
                    outLo[(long long)m * ldoh + n] = lo;
                    if (out32) out32[(long long)m * ldo32 + n] = v;
                }
}

// Encoder wavefront diagonal d: blockIdx.z = layer - l_base.
__global__ void __launch_bounds__(256, 2) enc_diag_kernel(
    int d, int l_base,
    const float* __restrict__ xraw, const float* __restrict__ Wih0,
    const float* __restrict__ ebih, const float* __restrict__ ebhh,
    float* __restrict__ enc_out)
{
    extern __shared__ __half sm[];
    const int l = l_base + blockIdx.z;
    const int t = d - l;
    const int bm0 = blockIdx.x * 64;
    const int bn0 = blockIdx.y * 64;

    const __half* Whi = g_wenc_hi + (long long)l * 524288;
    const __half* Wlo = g_wenc_lo + (long long)l * 524288;
    __half* actl_hi = g_act + ((long long)l * 2 + 0) * ACT_L;
    __half* actl_lo = g_act + ((long long)l * 2 + 1) * ACT_L;

    const __half *Xhi = nullptr, *Xlo = nullptr, *Hhi = nullptr, *Hlo = nullptr;
    long long ldx = 0;
    int kstart = 512, kend = 512;
    const float* Xr = nullptr;

    if (l == 0) {
        Xr = xraw + (long long)t * 6;
    } else {
        const __half* prev = g_act + ((long long)(l - 1) * 2) * ACT_L;
        Xhi = prev + (long long)t * 512;
        Xlo = prev + ACT_L + (long long)t * 512;
        ldx = 65536;
        kstart = 0;
    }
    if (t > 0) {
        Hhi = actl_hi + (long long)(t - 1) * 512;
        Hlo = actl_lo + (long long)(t - 1) * 512;
        kend = 1024;
    }
    float* o32 = (l == 3) ? enc_out + (long long)t * 512 : nullptr;

    step_core(sm, bm0, bn0, Xhi, Xlo, ldx, Hhi, Hlo, 65536,
              Whi, Wlo, ebih + l * 512, ebhh + l * 512,
              actl_hi + (long long)t * 512, actl_lo + (long long)t * 512, 65536,
              o32, 65536, kstart, kend, Xr, 768, Wih0);
}

__global__ void __launch_bounds__(256, 2) dec_step_kernel(
    const __half* __restrict__ Xhi, const __half* __restrict__ Xlo, long long ldx,
    const __half* __restrict__ Hhi, const __half* __restrict__ Hlo, long long ldh,
    const __half* __restrict__ Whi, const __half* __restrict__ Wlo,
    const float* __restrict__ bih, const float* __restrict__ bhh,
    __half* __restrict__ outHi, __half* __restrict__ outLo,
    float* __restrict__ out32, long long ldo32)
{
    extern __shared__ __half sm[];
    step_core(sm, blockIdx.x * 64, blockIdx.y * 64,
              Xhi, Xlo, ldx, Hhi, Hlo, ldh, Whi, Wlo, bih, bhh,
              outHi, outLo, 512, out32, ldo32, 0, 1024, nullptr, 0, nullptr);
}

// Split all weights once into fp16 hi/lo, layout [l][n][k] with k = [Wih|Whh].
__global__ void __launch_bounds__(256) prep_kernel(
    const float* __restrict__ eWih, const float* __restrict__ eWhh,
    const float* __restrict__ dWih, const float* __restrict__ dWhh)
{
    const unsigned idx = blockIdx.x * 256 + threadIdx.x;
    const int model = idx >> 21;
    const unsigned j = idx & 0x1FFFFFu;
    const int l = j >> 19;
    const int n = (j >> 10) & 511;
    const int k = j & 1023;
    float v;
    if (!model) {
        if (k < 512) v = (l == 0) ? 0.f : eWih[((unsigned)(l - 1) * 512 + n) * 512 + k];
        else         v = eWhh[((unsigned)l * 512 + n) * 512 + (k - 512)];
    } else {
        if (k < 512) v = dWih[((unsigned)l * 512 + n) * 512 + k];
        else         v = dWhh[((unsigned)l * 512 + n) * 512 + (k - 512)];
    }
    const __half hi = __float2half_rn(v);
    const __half lo = __float2half_rn(v - __half2float(hi));
    if (!model) { g_wenc_hi[j] = hi; g_wenc_lo[j] = lo; }
    else        { g_wdec_hi[j] = hi; g_wdec_lo[j] = lo; }
}

// outputs[r, n] = decout[r, :] @ fcW[n, :] + fcb[n]
__global__ void __launch_bounds__(256) fc_kernel(
    const float* __restrict__ in, const float* __restrict__ W,
    const float* __restrict__ b, float* __restrict__ out)
{
    __shared__ float Ws[6 * 512];
    const int tid = threadIdx.x;
    for (int i = tid; i < 6 * 512; i += 256) Ws[i] = W[i];
    __syncthreads();

    const int warp = tid >> 5, lane = tid & 31;
    const int row = blockIdx.x * 8 + warp;
    float p[6] = {0.f, 0.f, 0.f, 0.f, 0.f, 0.f};
    for (int k = lane; k < 512; k += 32) {
        const float v = in[(long long)row * 512 + k];
#pragma unroll
        for (int n = 0; n < 6; ++n) p[n] += v * Ws[n * 512 + k];
    }
#pragma unroll
    for (int off = 16; off > 0; off >>= 1)
#pragma unroll
        for (int n = 0; n < 6; ++n)
            p[n] += __shfl_down_sync(0xffffffffu, p[n], off);
    if (lane == 0) {
#pragma unroll
        for (int n = 0; n < 6; ++n) out[(long long)row * 6 + n] = p[n] + b[n];
    }
}

extern "C" void kernel_launch(void* const* d_in, const int* in_sizes, int n_in,
                              void* d_out, int out_size) {
    const float* x     = (const float*)d_in[0];
    const float* eWih0 = (const float*)d_in[1];
    const float* eWih  = (const float*)d_in[2];
    const float* eWhh  = (const float*)d_in[3];
    const float* ebih  = (const float*)d_in[4];
    const float* ebhh  = (const float*)d_in[5];
    const float* dWih  = (const float*)d_in[6];
    const float* dWhh  = (const float*)d_in[7];
    const float* dbih  = (const float*)d_in[8];
    const float* dbhh  = (const float*)d_in[9];
    const float* fcW   = (const float*)d_in[10];
    const float* fcb   = (const float*)d_in[11];

    float* out = (float*)d_out;
    float* enc_out = out;               // [1024,128,512]
    float* outputs = out + 67108864LL;  // [1024,10,6]

    __half *actB, *dhHi, *dhLo, *wdHi, *wdLo;
    float* decout;
    cudaGetSymbolAddress((void**)&actB, g_act);
    cudaGetSymbolAddress((void**)&dhHi, g_dh_hi);
    cudaGetSymbolAddress((void**)&dhLo, g_dh_lo);
    cudaGetSymbolAddress((void**)&wdHi, g_wdec_hi);
    cudaGetSymbolAddress((void**)&wdLo, g_wdec_lo);
    cudaGetSymbolAddress((void**)&decout, g_decout);

    cudaFuncSetAttribute(enc_diag_kernel,
                         cudaFuncAttributeMaxDynamicSharedMemorySize, SMEM_BYTES);
    cudaFuncSetAttribute(dec_step_kernel,
                         cudaFuncAttributeMaxDynamicSharedMemorySize, SMEM_BYTES);

    // 1) weight split (no transpose)
    prep_kernel<<<16384, 256>>>(eWih, eWhh, dWih, dWhh);

    // 2) encoder wavefront: 131 diagonals, 64x64 tiles
    for (int d = 0; d < 131; ++d) {
        const int llo = (d > 127) ? d - 127 : 0;
        const int lhi = (d < 3) ? d : 3;
        dim3 grid(16, 8, lhi - llo + 1);
        enc_diag_kernel<<<grid, 256, SMEM_BYTES>>>(d, llo, x, eWih0, ebih, ebhh,
                                                   enc_out);
    }

    // 3) decoder: 10 steps x 4 layers, serial
    const dim3 dgrid(16, 8);
    for (int s = 0; s < 10; ++s) {
        const int wset = s & 1;
        const int rset = (s - 1) & 1;
        for (int l = 0; l < 4; ++l) {
            const __half *Xhi, *Xlo, *Hhi, *Hlo;
            long long ldx, ldh;
            if (l == 0) {
                if (s == 0) {
                    Xhi = actB + 6 * ACT_L + 127LL * 512;
                    Xlo = actB + 7 * ACT_L + 127LL * 512;
                    ldx = 65536;
                } else {
                    Xhi = dhHi + ((long long)rset * 4 + 3) * 524288;
                    Xlo = dhLo + ((long long)rset * 4 + 3) * 524288;
                    ldx = 512;
                }
            } else {
                Xhi = dhHi + ((long long)wset * 4 + (l - 1)) * 524288;
                Xlo = dhLo + ((long long)wset * 4 + (l - 1)) * 524288;
                ldx = 512;
            }
            if (s == 0) {
                Hhi = actB + ((long long)l * 2 + 0) * ACT_L + 127LL * 512;
                Hlo = actB + ((long long)l * 2 + 1) * ACT_L + 127LL * 512;
                ldh = 65536;
            } else {
                Hhi = dhHi + ((long long)rset * 4 + l) * 524288;
                Hlo = dhLo + ((long long)rset * 4 + l) * 524288;
                ldh = 512;
            }
            __half* oHi = dhHi + ((long long)wset * 4 + l) * 524288;
            __half* oLo = dhLo + ((long long)wset * 4 + l) * 524288;
            float* o32 = (l == 3) ? decout + (long long)s * 512 : nullptr;
            dec_step_kernel<<<dgrid, 256, SMEM_BYTES>>>(
                Xhi, Xlo, ldx, Hhi, Hlo, ldh,
                wdHi + (long long)l * 524288, wdLo + (long long)l * 524288,
                dbih + l * 512, dbhh + l * 512, oHi, oLo, o32, 5120);
        }
    }

    // 4) FC head
    fc_kernel<<<1280, 256>>>(decout, fcW, fcb, outputs);
}